// round 12
// baseline (speedup 1.0000x reference)
#include <cuda_runtime.h>
#include <math.h>
#include <stdint.h>

// Problem constants (inputs: [8192, 64] fp32)
#define S        8192
#define E        64
#define CAP      256              // floor(2.0 * 8192 / 64) = 256
#define CHUNK    128
#define NCHUNK   (S / CHUNK)      // 64
#define ROW      (E * CAP)        // 16384 floats per token row
#define CB_ELEMS (S * E * CAP)    // 134,217,728

// -------- allocation-free scratch (device globals) --------
__device__ int   g_top1[S];
__device__ int   g_top2[S];
__device__ float g_w1[S];
__device__ float g_w2[S];
__device__ int   g_hist1[NCHUNK * E];
__device__ int   g_hist2[NCHUNK * E];
__device__ int   g_off1[NCHUNK * E];
__device__ int   g_off2[NCHUNK * E];
__device__ int   g_total1[E];
__device__ int   g_pos1[S];       // flat e*CAP + rank, or -1 if dropped
__device__ int   g_pos2[S];

// ---------------------------------------------------------------------------
// Kernel 1: per-token softmax + top1/top2. One warp per token, lanes own
// columns {lane, lane+32}. Tie-break = smallest index (jnp.argmax semantics).
// ---------------------------------------------------------------------------
__global__ void router_kernel(const float* __restrict__ in) {
    int warp = (blockIdx.x * blockDim.x + threadIdx.x) >> 5;
    int lane = threadIdx.x & 31;
    if (warp >= S) return;

    const float* row = in + (size_t)warp * E;
    float x0 = row[lane];
    float x1 = row[lane + 32];

    // ---- top1 argmax ----
    float bv; int bi;
    if (x0 >= x1) { bv = x0; bi = lane; } else { bv = x1; bi = lane + 32; }
#pragma unroll
    for (int o = 16; o > 0; o >>= 1) {
        float ov = __shfl_xor_sync(0xffffffffu, bv, o);
        int   oi = __shfl_xor_sync(0xffffffffu, bi, o);
        if (ov > bv || (ov == bv && oi < bi)) { bv = ov; bi = oi; }
    }
    float m1 = bv;
    int   i1 = bi;

    // ---- softmax denominator (max-subtracted) ----
    float sum = expf(x0 - m1) + expf(x1 - m1);
#pragma unroll
    for (int o = 16; o > 0; o >>= 1)
        sum += __shfl_xor_sync(0xffffffffu, sum, o);

    // ---- top2 argmax with top1 index masked to -inf ----
    float y0 = (lane == i1)        ? -INFINITY : x0;
    float y1 = ((lane + 32) == i1) ? -INFINITY : x1;
    float bv2; int bi2;
    if (y0 >= y1) { bv2 = y0; bi2 = lane; } else { bv2 = y1; bi2 = lane + 32; }
#pragma unroll
    for (int o = 16; o > 0; o >>= 1) {
        float ov = __shfl_xor_sync(0xffffffffu, bv2, o);
        int   oi = __shfl_xor_sync(0xffffffffu, bi2, o);
        if (ov > bv2 || (ov == bv2 && oi < bi2)) { bv2 = ov; bi2 = oi; }
    }

    if (lane == 0) {
        g_top1[warp] = i1;
        g_top2[warp] = bi2;
        g_w1[warp]   = 1.0f / sum;
        g_w2[warp]   = expf(bv2 - m1) / sum;
    }
}

// ---------------------------------------------------------------------------
// Kernel 2: per-chunk histograms of top1/top2 expert assignments.
// ---------------------------------------------------------------------------
__global__ void hist_kernel() {
    __shared__ int s1[CHUNK];
    __shared__ int s2[CHUNK];
    int c = blockIdx.x;
    int t = threadIdx.x;
    s1[t] = g_top1[c * CHUNK + t];
    s2[t] = g_top2[c * CHUNK + t];
    __syncthreads();
    if (t < E) {
        int c1 = 0, c2 = 0;
#pragma unroll 8
        for (int i = 0; i < CHUNK; i++) {
            c1 += (s1[i] == t);
            c2 += (s2[i] == t);
        }
        g_hist1[c * E + t] = c1;
        g_hist2[c * E + t] = c2;
    }
}

// ---------------------------------------------------------------------------
// Kernel 3: exclusive prefix over chunks per expert + total top1 counts.
// ---------------------------------------------------------------------------
__global__ void scan_kernel() {
    int e = threadIdx.x;
    int r1 = 0, r2 = 0;
    for (int c = 0; c < NCHUNK; c++) {
        g_off1[c * E + e] = r1;  r1 += g_hist1[c * E + e];
        g_off2[c * E + e] = r2;  r2 += g_hist2[c * E + e];
    }
    g_total1[e] = r1;
}

// ---------------------------------------------------------------------------
// Kernel 4: within-chunk sequential ranking -> per-token flat positions.
// Thread-per-expert walks its chunk's 128 tokens in order (cumsum semantics).
// ---------------------------------------------------------------------------
__global__ void pos_kernel() {
    __shared__ int s1[CHUNK];
    __shared__ int s2[CHUNK];
    int c = blockIdx.x;
    int t = threadIdx.x;
    int tok = c * CHUNK + t;
    s1[t] = g_top1[tok];
    s2[t] = g_top2[tok];
    __syncthreads();

    if (t < E) {
        const int e = t;
        int ctr1 = g_off1[c * E + e];
        int ctr2 = g_total1[e] + g_off2[c * E + e];
        for (int i = 0; i < CHUNK; i++) {
            int tk = c * CHUNK + i;
            if (s1[i] == e) {
                int r = ctr1++;
                g_pos1[tk] = (r < CAP) ? (e * CAP + r) : -1;
            }
            if (s2[i] == e) {
                int r = ctr2++;
                g_pos2[tk] = (r < CAP) ? (e * CAP + r) : -1;
            }
        }
    }
}

// ---------------------------------------------------------------------------
// Kernel 5a: pure streaming zero-fill (no dependence on routing). One block
// per token row; float4 streaming stores at the LTS cap.
// ---------------------------------------------------------------------------
__global__ void __launch_bounds__(256) zero_kernel(float* __restrict__ out,
                                                   int has_mask) {
    int tok = blockIdx.x;
    size_t wbase = (size_t)tok * ROW;
    float4* w4 = (float4*)(out + wbase);
    float4* m4 = (float4*)(out + (size_t)CB_ELEMS + wbase);
    const float4 z = make_float4(0.f, 0.f, 0.f, 0.f);

    if (has_mask) {
#pragma unroll
        for (int i = 0; i < ROW / 4 / 256; i++) {       // 16 iters
            __stcs(&w4[i * 256 + threadIdx.x], z);
            __stcs(&m4[i * 256 + threadIdx.x], z);
        }
    } else {
#pragma unroll
        for (int i = 0; i < ROW / 4 / 256; i++)
            __stcs(&w4[i * 256 + threadIdx.x], z);
    }
}

// ---------------------------------------------------------------------------
// Kernel 5b: patch the <=2 nonzero positions per token (after zero + pos).
// ---------------------------------------------------------------------------
__global__ void patch_kernel(float* __restrict__ out, int has_mask) {
    int tok = blockIdx.x * blockDim.x + threadIdx.x;
    if (tok >= S) return;
    size_t wbase = (size_t)tok * ROW;

    int p1 = g_pos1[tok];
    if (p1 >= 0) {
        out[wbase + p1] = g_w1[tok];
        if (has_mask) out[(size_t)CB_ELEMS + wbase + p1] = 1.0f;
    }
    int p2 = g_pos2[tok];
    if (p2 >= 0) {
        out[wbase + p2] = g_w2[tok];
        if (has_mask) out[(size_t)CB_ELEMS + wbase + p2] = 1.0f;
    }
}

// ---------------------------------------------------------------------------
extern "C" void kernel_launch(void* const* d_in, const int* in_sizes, int n_in,
                              void* d_out, int out_size) {
    const float* in  = (const float*)d_in[0];
    float*       out = (float*)d_out;
    int has_mask = (out_size >= 2 * CB_ELEMS) ? 1 : 0;

    // Side stream + events, created once on the first (uncaptured,
    // correctness) call and reused by every captured call. Same kernels,
    // same work, every invocation — deterministic.
    static cudaStream_t s_side = nullptr;
    static cudaEvent_t  s_fork = nullptr, s_join = nullptr;
    if (s_side == nullptr) {
        cudaStreamCreateWithFlags(&s_side, cudaStreamNonBlocking);
        cudaEventCreateWithFlags(&s_fork, cudaEventDisableTiming);
        cudaEventCreateWithFlags(&s_join, cudaEventDisableTiming);
    }

    // Fork: routing chain on the side stream, bulk zero on the main stream.
    cudaEventRecord(s_fork, 0);
    cudaStreamWaitEvent(s_side, s_fork, 0);

    router_kernel<<<S / 8, 256, 0, s_side>>>(in);
    hist_kernel<<<NCHUNK, CHUNK, 0, s_side>>>();
    scan_kernel<<<1, E, 0, s_side>>>();
    pos_kernel<<<NCHUNK, CHUNK, 0, s_side>>>();
    cudaEventRecord(s_join, s_side);

    zero_kernel<<<S, 256>>>(out, has_mask);   // ~160us, hides the 13us chain

    // Join: patch needs both the zeros and the positions.
    cudaStreamWaitEvent(0, s_join, 0);
    patch_kernel<<<S / 256, 256>>>(out, has_mask);
}

// round 13
// speedup vs baseline: 1.0007x; 1.0007x over previous
#include <cuda_runtime.h>
#include <math.h>
#include <stdint.h>

// Problem constants (inputs: [8192, 64] fp32)
#define S        8192
#define E        64
#define CAP      256              // floor(2.0 * 8192 / 64) = 256
#define CHUNK    128
#define NCHUNK   (S / CHUNK)      // 64
#define ROW      (E * CAP)        // 16384 floats per token row
#define CB_ELEMS (S * E * CAP)    // 134,217,728

// -------- allocation-free scratch (device globals) --------
__device__ int   g_top1[S];
__device__ int   g_top2[S];
__device__ float g_w1[S];
__device__ float g_w2[S];
__device__ int   g_hist1[NCHUNK * E];
__device__ int   g_hist2[NCHUNK * E];
__device__ int   g_off1[NCHUNK * E];
__device__ int   g_off2[NCHUNK * E];
__device__ int   g_total1[E];
__device__ int   g_pos1[S];       // flat e*CAP + rank, or -1 if dropped
__device__ int   g_pos2[S];

// ---------------------------------------------------------------------------
// Kernel 1: per-token softmax + top1/top2. One warp per token, lanes own
// columns {lane, lane+32}. Tie-break = smallest index (jnp.argmax semantics).
// ---------------------------------------------------------------------------
__global__ void router_kernel(const float* __restrict__ in) {
    int warp = (blockIdx.x * blockDim.x + threadIdx.x) >> 5;
    int lane = threadIdx.x & 31;
    if (warp >= S) return;

    const float* row = in + (size_t)warp * E;
    float x0 = row[lane];
    float x1 = row[lane + 32];

    // ---- top1 argmax ----
    float bv; int bi;
    if (x0 >= x1) { bv = x0; bi = lane; } else { bv = x1; bi = lane + 32; }
#pragma unroll
    for (int o = 16; o > 0; o >>= 1) {
        float ov = __shfl_xor_sync(0xffffffffu, bv, o);
        int   oi = __shfl_xor_sync(0xffffffffu, bi, o);
        if (ov > bv || (ov == bv && oi < bi)) { bv = ov; bi = oi; }
    }
    float m1 = bv;
    int   i1 = bi;

    // ---- softmax denominator (max-subtracted) ----
    float sum = expf(x0 - m1) + expf(x1 - m1);
#pragma unroll
    for (int o = 16; o > 0; o >>= 1)
        sum += __shfl_xor_sync(0xffffffffu, sum, o);

    // ---- top2 argmax with top1 index masked to -inf ----
    float y0 = (lane == i1)        ? -INFINITY : x0;
    float y1 = ((lane + 32) == i1) ? -INFINITY : x1;
    float bv2; int bi2;
    if (y0 >= y1) { bv2 = y0; bi2 = lane; } else { bv2 = y1; bi2 = lane + 32; }
#pragma unroll
    for (int o = 16; o > 0; o >>= 1) {
        float ov = __shfl_xor_sync(0xffffffffu, bv2, o);
        int   oi = __shfl_xor_sync(0xffffffffu, bi2, o);
        if (ov > bv2 || (ov == bv2 && oi < bi2)) { bv2 = ov; bi2 = oi; }
    }

    if (lane == 0) {
        g_top1[warp] = i1;
        g_top2[warp] = bi2;
        g_w1[warp]   = 1.0f / sum;
        g_w2[warp]   = expf(bv2 - m1) / sum;
    }
}

// ---------------------------------------------------------------------------
// Kernel 2: per-chunk histograms of top1/top2 expert assignments.
// ---------------------------------------------------------------------------
__global__ void hist_kernel() {
    __shared__ int s1[CHUNK];
    __shared__ int s2[CHUNK];
    int c = blockIdx.x;
    int t = threadIdx.x;
    s1[t] = g_top1[c * CHUNK + t];
    s2[t] = g_top2[c * CHUNK + t];
    __syncthreads();
    if (t < E) {
        int c1 = 0, c2 = 0;
#pragma unroll 8
        for (int i = 0; i < CHUNK; i++) {
            c1 += (s1[i] == t);
            c2 += (s2[i] == t);
        }
        g_hist1[c * E + t] = c1;
        g_hist2[c * E + t] = c2;
    }
}

// ---------------------------------------------------------------------------
// Kernel 3: exclusive prefix over chunks per expert + total top1 counts.
// ---------------------------------------------------------------------------
__global__ void scan_kernel() {
    int e = threadIdx.x;
    int r1 = 0, r2 = 0;
    for (int c = 0; c < NCHUNK; c++) {
        g_off1[c * E + e] = r1;  r1 += g_hist1[c * E + e];
        g_off2[c * E + e] = r2;  r2 += g_hist2[c * E + e];
    }
    g_total1[e] = r1;
}

// ---------------------------------------------------------------------------
// Kernel 4: within-chunk sequential ranking -> per-token flat positions.
// Thread-per-expert walks its chunk's 128 tokens in order (cumsum semantics).
// ---------------------------------------------------------------------------
__global__ void pos_kernel() {
    __shared__ int s1[CHUNK];
    __shared__ int s2[CHUNK];
    int c = blockIdx.x;
    int t = threadIdx.x;
    int tok = c * CHUNK + t;
    s1[t] = g_top1[tok];
    s2[t] = g_top2[tok];
    __syncthreads();

    if (t < E) {
        const int e = t;
        int ctr1 = g_off1[c * E + e];
        int ctr2 = g_total1[e] + g_off2[c * E + e];
        for (int i = 0; i < CHUNK; i++) {
            int tk = c * CHUNK + i;
            if (s1[i] == e) {
                int r = ctr1++;
                g_pos1[tk] = (r < CAP) ? (e * CAP + r) : -1;
            }
            if (s2[i] == e) {
                int r = ctr2++;
                g_pos2[tk] = (r < CAP) ? (e * CAP + r) : -1;
            }
        }
    }
}

// ---------------------------------------------------------------------------
// Kernel 5a: pure streaming zero-fill (no dependence on routing). One block
// per token row; float4 streaming stores at the LTS cap.
// ---------------------------------------------------------------------------
__global__ void __launch_bounds__(256) zero_kernel(float* __restrict__ out,
                                                   int has_mask) {
    int tok = blockIdx.x;
    size_t wbase = (size_t)tok * ROW;
    float4* w4 = (float4*)(out + wbase);
    float4* m4 = (float4*)(out + (size_t)CB_ELEMS + wbase);
    const float4 z = make_float4(0.f, 0.f, 0.f, 0.f);

    if (has_mask) {
#pragma unroll
        for (int i = 0; i < ROW / 4 / 256; i++) {       // 16 iters
            __stcs(&w4[i * 256 + threadIdx.x], z);
            __stcs(&m4[i * 256 + threadIdx.x], z);
        }
    } else {
#pragma unroll
        for (int i = 0; i < ROW / 4 / 256; i++)
            __stcs(&w4[i * 256 + threadIdx.x], z);
    }
}

// ---------------------------------------------------------------------------
// Kernel 5b: patch the <=2 nonzero positions per token (after zero + pos).
// ---------------------------------------------------------------------------
__global__ void patch_kernel(float* __restrict__ out, int has_mask) {
    int tok = blockIdx.x * blockDim.x + threadIdx.x;
    if (tok >= S) return;
    size_t wbase = (size_t)tok * ROW;

    int p1 = g_pos1[tok];
    if (p1 >= 0) {
        out[wbase + p1] = g_w1[tok];
        if (has_mask) out[(size_t)CB_ELEMS + wbase + p1] = 1.0f;
    }
    int p2 = g_pos2[tok];
    if (p2 >= 0) {
        out[wbase + p2] = g_w2[tok];
        if (has_mask) out[(size_t)CB_ELEMS + wbase + p2] = 1.0f;
    }
}

// ---------------------------------------------------------------------------
extern "C" void kernel_launch(void* const* d_in, const int* in_sizes, int n_in,
                              void* d_out, int out_size) {
    const float* in  = (const float*)d_in[0];
    float*       out = (float*)d_out;
    int has_mask = (out_size >= 2 * CB_ELEMS) ? 1 : 0;

    // Side stream + events, created once on the first (uncaptured,
    // correctness) call and reused by every captured call. Same kernels,
    // same work, every invocation — deterministic.
    static cudaStream_t s_side = nullptr;
    static cudaEvent_t  s_fork = nullptr, s_join = nullptr;
    if (s_side == nullptr) {
        cudaStreamCreateWithFlags(&s_side, cudaStreamNonBlocking);
        cudaEventCreateWithFlags(&s_fork, cudaEventDisableTiming);
        cudaEventCreateWithFlags(&s_join, cudaEventDisableTiming);
    }

    // Fork: routing chain on the side stream, bulk zero on the main stream.
    cudaEventRecord(s_fork, 0);
    cudaStreamWaitEvent(s_side, s_fork, 0);

    router_kernel<<<S / 8, 256, 0, s_side>>>(in);
    hist_kernel<<<NCHUNK, CHUNK, 0, s_side>>>();
    scan_kernel<<<1, E, 0, s_side>>>();
    pos_kernel<<<NCHUNK, CHUNK, 0, s_side>>>();
    cudaEventRecord(s_join, s_side);

    zero_kernel<<<S, 256>>>(out, has_mask);   // ~160us, hides the 13us chain

    // Join: patch needs both the zeros and the positions.
    cudaStreamWaitEvent(0, s_join, 0);
    patch_kernel<<<S / 256, 256>>>(out, has_mask);
}

// round 14
// speedup vs baseline: 1.1614x; 1.1606x over previous
#include <cuda_runtime.h>
#include <math.h>
#include <stdint.h>

// Problem constants (inputs: [8192, 64] fp32)
#define S        8192
#define E        64
#define CAP      256              // floor(2.0 * 8192 / 64) = 256
#define CHUNK    32
#define NCHUNK   (S / CHUNK)      // 256
#define ROW      (E * CAP)        // 16384 floats per token row
#define CB_ELEMS (S * E * CAP)    // 134,217,728

// -------- allocation-free scratch (device globals) --------
__device__ int   g_top1[S];
__device__ int   g_top2[S];
__device__ float g_w1[S];
__device__ float g_w2[S];
__device__ int   g_hist1[NCHUNK * E];
__device__ int   g_hist2[NCHUNK * E];
__device__ int   g_off1[NCHUNK * E];   // exclusive cumsum over chunks
__device__ int   g_off2[NCHUNK * E];
__device__ int   g_total1[E];          // total top1 count per expert

// ---------------------------------------------------------------------------
// Kernel 1: fused router + per-chunk histogram.
// Block = 32 warps = 32 tokens = exactly one chunk. Each warp does softmax +
// top1/top2 for its token (lanes own columns {lane, lane+32}; argmax
// tie-break = smallest index, matching jnp.argmax). Then threads [0,64)
// count this chunk's expert assignments.
// ---------------------------------------------------------------------------
__global__ void __launch_bounds__(1024) router_hist_kernel(
        const float* __restrict__ in) {
    __shared__ int sh1[CHUNK];
    __shared__ int sh2[CHUNK];

    int wid  = threadIdx.x >> 5;
    int lane = threadIdx.x & 31;
    int tok  = blockIdx.x * CHUNK + wid;

    const float* row = in + (size_t)tok * E;
    float x0 = row[lane];
    float x1 = row[lane + 32];

    // ---- top1 argmax ----
    float bv; int bi;
    if (x0 >= x1) { bv = x0; bi = lane; } else { bv = x1; bi = lane + 32; }
#pragma unroll
    for (int o = 16; o > 0; o >>= 1) {
        float ov = __shfl_xor_sync(0xffffffffu, bv, o);
        int   oi = __shfl_xor_sync(0xffffffffu, bi, o);
        if (ov > bv || (ov == bv && oi < bi)) { bv = ov; bi = oi; }
    }
    float m1 = bv;
    int   i1 = bi;

    // ---- softmax denominator (max-subtracted) ----
    float sum = expf(x0 - m1) + expf(x1 - m1);
#pragma unroll
    for (int o = 16; o > 0; o >>= 1)
        sum += __shfl_xor_sync(0xffffffffu, sum, o);

    // ---- top2 argmax with top1 index masked to -inf ----
    float y0 = (lane == i1)        ? -INFINITY : x0;
    float y1 = ((lane + 32) == i1) ? -INFINITY : x1;
    float bv2; int bi2;
    if (y0 >= y1) { bv2 = y0; bi2 = lane; } else { bv2 = y1; bi2 = lane + 32; }
#pragma unroll
    for (int o = 16; o > 0; o >>= 1) {
        float ov = __shfl_xor_sync(0xffffffffu, bv2, o);
        int   oi = __shfl_xor_sync(0xffffffffu, bi2, o);
        if (ov > bv2 || (ov == bv2 && oi < bi2)) { bv2 = ov; bi2 = oi; }
    }

    if (lane == 0) {
        g_top1[tok] = i1;
        g_top2[tok] = bi2;
        g_w1[tok]   = 1.0f / sum;
        g_w2[tok]   = expf(bv2 - m1) / sum;
        sh1[wid] = i1;
        sh2[wid] = bi2;
    }
    __syncthreads();

    // per-chunk histogram: thread t counts expert t over 32 chunk tokens
    if (threadIdx.x < E) {
        int t = threadIdx.x;
        int c1 = 0, c2 = 0;
#pragma unroll
        for (int i = 0; i < CHUNK; i++) {
            c1 += (sh1[i] == t);
            c2 += (sh2[i] == t);
        }
        g_hist1[blockIdx.x * E + t] = c1;
        g_hist2[blockIdx.x * E + t] = c2;
    }
}

// ---------------------------------------------------------------------------
// Kernel 2: exclusive scan over 256 chunks, one block per expert
// (Hillis-Steele in shared). Also emits total top1 count per expert.
// ---------------------------------------------------------------------------
__global__ void __launch_bounds__(NCHUNK) scan_kernel() {
    __shared__ int sh[NCHUNK];
    int e = blockIdx.x;
    int c = threadIdx.x;

    // ---- scan hist1 ----
    int v1 = g_hist1[c * E + e];
    sh[c] = v1;
    __syncthreads();
    int acc = v1;
#pragma unroll
    for (int o = 1; o < NCHUNK; o <<= 1) {
        int other = (c >= o) ? sh[c - o] : 0;
        __syncthreads();
        acc += other;
        sh[c] = acc;
        __syncthreads();
    }
    g_off1[c * E + e] = acc - v1;                  // exclusive
    if (c == NCHUNK - 1) g_total1[e] = acc;
    __syncthreads();

    // ---- scan hist2 ----
    int v2 = g_hist2[c * E + e];
    sh[c] = v2;
    __syncthreads();
    acc = v2;
#pragma unroll
    for (int o = 1; o < NCHUNK; o <<= 1) {
        int other = (c >= o) ? sh[c - o] : 0;
        __syncthreads();
        acc += other;
        sh[c] = acc;
        __syncthreads();
    }
    g_off2[c * E + e] = acc - v2;
}

// ---------------------------------------------------------------------------
// Kernel 3: fused zero-fill + in-block rank computation + patch.
// One block per token row. All 256 threads stream zeros (float4, streaming
// hint); after the block barrier, warp 0 computes this token's ranks with a
// single ballot over its 32-token chunk and patches the <=2 nonzeros.
// No cross-block hazards (each block owns its row).
// ---------------------------------------------------------------------------
__global__ void __launch_bounds__(256) fill_kernel(float* __restrict__ out,
                                                   int has_mask) {
    int tok = blockIdx.x;
    size_t wbase = (size_t)tok * ROW;
    float4* w4 = (float4*)(out + wbase);
    float4* m4 = (float4*)(out + (size_t)CB_ELEMS + wbase);
    const float4 z = make_float4(0.f, 0.f, 0.f, 0.f);

    if (has_mask) {
#pragma unroll
        for (int i = 0; i < ROW / 4 / 256; i++) {       // 16 iters
            __stcs(&w4[i * 256 + threadIdx.x], z);
            __stcs(&m4[i * 256 + threadIdx.x], z);
        }
    } else {
#pragma unroll
        for (int i = 0; i < ROW / 4 / 256; i++)
            __stcs(&w4[i * 256 + threadIdx.x], z);
    }
    __syncthreads();   // zeros ordered before the patch (same block)

    if (threadIdx.x < 32) {
        int lane  = threadIdx.x;
        int chunk = tok >> 5;
        int tpos  = tok & 31;
        unsigned ltmask = (1u << tpos) - 1u;

        int t1 = g_top1[(chunk << 5) + lane];
        int t2 = g_top2[(chunk << 5) + lane];
        int e1 = __shfl_sync(0xffffffffu, t1, tpos);
        int e2 = __shfl_sync(0xffffffffu, t2, tpos);

        unsigned m1 = __ballot_sync(0xffffffffu, t1 == e1);
        unsigned m2 = __ballot_sync(0xffffffffu, t2 == e2);

        if (lane == 0) {
            int r1 = g_off1[chunk * E + e1] + __popc(m1 & ltmask);
            int r2 = g_total1[e2] + g_off2[chunk * E + e2] + __popc(m2 & ltmask);
            if (r1 < CAP) {
                size_t o = wbase + (size_t)e1 * CAP + r1;
                out[o] = g_w1[tok];
                if (has_mask) out[(size_t)CB_ELEMS + o] = 1.0f;
            }
            if (r2 < CAP) {
                size_t o = wbase + (size_t)e2 * CAP + r2;
                out[o] = g_w2[tok];
                if (has_mask) out[(size_t)CB_ELEMS + o] = 1.0f;
            }
        }
    }
}

// ---------------------------------------------------------------------------
extern "C" void kernel_launch(void* const* d_in, const int* in_sizes, int n_in,
                              void* d_out, int out_size) {
    const float* in  = (const float*)d_in[0];
    float*       out = (float*)d_out;
    int has_mask = (out_size >= 2 * CB_ELEMS) ? 1 : 0;

    router_hist_kernel<<<NCHUNK, 1024>>>(in);   // 32 tokens (1 chunk) / block
    scan_kernel<<<E, NCHUNK>>>();               // block per expert
    fill_kernel<<<S, 256>>>(out, has_mask);     // fused zero + rank + patch
}